// round 8
// baseline (speedup 1.0000x reference)
#include <cuda_runtime.h>
#include <cuda_bf16.h>
#include <math.h>

#define BB 256
#define HH 512
#define EE 512
#define VV 10000
#define TT 48
#define TTOT 9436

// ---------------- scratch (device globals; no allocation allowed) -------------
__device__ float g_Xc[BB * 2048];          // conv output flattened [B,2048]
__device__ float g_F0[BB * HH];            // pre-BN fc output
__device__ float g_F[BB * HH];             // BN'd features
__device__ float g_Emb[TTOT * EE];         // packed caption embeddings
__device__ float g_Xpad[TT * BB * EE];     // padded [T,B,E]
__device__ float g_xA[TT * BB * HH];       // x_t @ attn_w_x^T + attn_b
__device__ float g_xC[TT * BB * HH];       // x_t @ comb_w_x^T + comb_b
__device__ float g_hx[BB * HH];
__device__ float g_GhL[BB * 2048];         // [Gh(1536) | attn logits h-part(512)]
__device__ float g_Gi[BB * 3 * HH];
__device__ float g_applied[BB * HH];
__device__ float g_inp[BB * HH];
__device__ float g_Cat[BB * 2 * HH];
__device__ float g_Y[BB * 2 * HH];
__device__ float g_Wpack[2048 * 512];      // rows 0..1535: gru_whh; 1536..2047: attn_w[:,512:]
__device__ float g_Xt[16384 * 2048];       // transposed features [b*64+s][cin]
__device__ float g_CW[320 * 2048];         // conv weights remapped [co*9+tap][cin]
__device__ float g_ConvC[16384 * 320];     // per-tap conv partial sums

// ---------------- bf16 helpers -------------------------------------------------
__device__ __forceinline__ void mma_bf16(float c[4],
    unsigned a0, unsigned a1, unsigned a2, unsigned a3,
    unsigned b0, unsigned b1)
{
    asm volatile(
        "mma.sync.aligned.m16n8k16.row.col.f32.bf16.bf16.f32 "
        "{%0,%1,%2,%3}, {%4,%5,%6,%7}, {%8,%9}, {%0,%1,%2,%3};"
        : "+f"(c[0]), "+f"(c[1]), "+f"(c[2]), "+f"(c[3])
        : "r"(a0), "r"(a1), "r"(a2), "r"(a3), "r"(b0), "r"(b1));
}

// split float4 into packed bf16x2 hi/lo pairs (2 uints each)
__device__ __forceinline__ void split4(const float4 v,
    unsigned& h0, unsigned& h1, unsigned& l0, unsigned& l1)
{
    float f[4] = {v.x, v.y, v.z, v.w};
    __nv_bfloat16 hb[4], lb[4];
#pragma unroll
    for (int i = 0; i < 4; i++) {
        hb[i] = __float2bfloat16_rn(f[i]);
        lb[i] = __float2bfloat16_rn(f[i] - __bfloat162float(hb[i]));
    }
    __nv_bfloat162 t;
    t = __halves2bfloat162(hb[0], hb[1]); h0 = *reinterpret_cast<unsigned*>(&t);
    t = __halves2bfloat162(hb[2], hb[3]); h1 = *reinterpret_cast<unsigned*>(&t);
    t = __halves2bfloat162(lb[0], lb[1]); l0 = *reinterpret_cast<unsigned*>(&t);
    t = __halves2bfloat162(lb[2], lb[3]); l1 = *reinterpret_cast<unsigned*>(&t);
}

// ---------------- BF16x3 GEMM, 2-stage smem pipeline ---------------------------
// C[M,N] = A[M,K] @ W[N,K]^T (+bias)(+add)(relu)
// BM=BN=64, BK=16, 128 threads (4 warps, 2x2), warp tile 32x32.
// Requires: N % 64 == 0, K % 16 == 0, lda/ldw % 4 == 0. M guarded.
__global__ __launch_bounds__(128) void tgemm_kernel(
    const float* __restrict__ A, int lda,
    const float* __restrict__ W, int ldw,
    const float* __restrict__ bias,
    const float* __restrict__ add,
    float* __restrict__ C, int ldc,
    int M, int N, int K, int act)
{
    __shared__ unsigned sAh[2][64 * 12], sAl[2][64 * 12];
    __shared__ unsigned sWh[2][64 * 12], sWl[2][64 * 12];

    const int tid  = threadIdx.x;
    const int lane = tid & 31;
    const int warp = tid >> 5;
    const int wm = (warp & 1) * 32;
    const int wn = (warp >> 1) * 32;
    const int m0 = blockIdx.y * 64;
    const int n0 = blockIdx.x * 64;

    const int lr = tid >> 2;          // 0..31 -> rows lr, lr+32
    const int lc = (tid & 3) * 4;     // k offset 0,4,8,12 (floats)
    const int lcu = lc >> 1;          // uint col 0,2,4,6

    float acc[2][4][4];
#pragma unroll
    for (int mt = 0; mt < 2; mt++)
#pragma unroll
        for (int nt = 0; nt < 4; nt++)
#pragma unroll
            for (int i = 0; i < 4; i++) acc[mt][nt][i] = 0.f;

    const int ar0 = m0 + lr, ar1 = m0 + lr + 32;
    const int wr0 = n0 + lr, wr1 = n0 + lr + 32;

    float4 av0, av1, wv0, wv1;
    const float4 z4 = make_float4(0.f, 0.f, 0.f, 0.f);

    // prologue: load k-tile 0 and store into buffer 0
    av0 = (ar0 < M) ? *(const float4*)(A + (size_t)ar0 * lda + lc) : z4;
    av1 = (ar1 < M) ? *(const float4*)(A + (size_t)ar1 * lda + lc) : z4;
    wv0 = *(const float4*)(W + (size_t)wr0 * ldw + lc);
    wv1 = *(const float4*)(W + (size_t)wr1 * ldw + lc);
    {
        unsigned h0, h1, l0, l1;
        split4(av0, h0, h1, l0, l1);
        *(uint2*)&sAh[0][lr * 12 + lcu] = make_uint2(h0, h1);
        *(uint2*)&sAl[0][lr * 12 + lcu] = make_uint2(l0, l1);
        split4(av1, h0, h1, l0, l1);
        *(uint2*)&sAh[0][(lr + 32) * 12 + lcu] = make_uint2(h0, h1);
        *(uint2*)&sAl[0][(lr + 32) * 12 + lcu] = make_uint2(l0, l1);
        split4(wv0, h0, h1, l0, l1);
        *(uint2*)&sWh[0][lr * 12 + lcu] = make_uint2(h0, h1);
        *(uint2*)&sWl[0][lr * 12 + lcu] = make_uint2(l0, l1);
        split4(wv1, h0, h1, l0, l1);
        *(uint2*)&sWh[0][(lr + 32) * 12 + lcu] = make_uint2(h0, h1);
        *(uint2*)&sWl[0][(lr + 32) * 12 + lcu] = make_uint2(l0, l1);
    }
    __syncthreads();

    const int krow = lane >> 2;   // 0..7
    const int kcol = lane & 3;    // 0..3 (uint cols; pairs k=2c,2c+1)
    const int nIter = K >> 4;

    for (int it = 0; it < nIter; it++) {
        const int cur = it & 1;
        const unsigned* Ah = sAh[cur];
        const unsigned* Al = sAl[cur];
        const unsigned* Wh = sWh[cur];
        const unsigned* Wl = sWl[cur];

        // issue global loads for next k-tile (latency hidden by MMAs below)
        const bool more = (it + 1 < nIter);
        if (more) {
            int k2 = (it + 1) * 16 + lc;
            av0 = (ar0 < M) ? *(const float4*)(A + (size_t)ar0 * lda + k2) : z4;
            av1 = (ar1 < M) ? *(const float4*)(A + (size_t)ar1 * lda + k2) : z4;
            wv0 = *(const float4*)(W + (size_t)wr0 * ldw + k2);
            wv1 = *(const float4*)(W + (size_t)wr1 * ldw + k2);
        }

        // compute on buf[cur]
        {
            unsigned ah[2][4], al_[2][4], bh[4][2], bl[4][2];
#pragma unroll
            for (int mt = 0; mt < 2; mt++) {
                int r = wm + mt * 16 + krow;
                int o0 = r * 12 + kcol;
                int o1 = (r + 8) * 12 + kcol;
                ah[mt][0] = Ah[o0];     ah[mt][1] = Ah[o1];
                ah[mt][2] = Ah[o0 + 4]; ah[mt][3] = Ah[o1 + 4];
                al_[mt][0] = Al[o0];     al_[mt][1] = Al[o1];
                al_[mt][2] = Al[o0 + 4]; al_[mt][3] = Al[o1 + 4];
            }
#pragma unroll
            for (int nt = 0; nt < 4; nt++) {
                int cn = wn + nt * 8 + krow;
                int o = cn * 12 + kcol;
                bh[nt][0] = Wh[o]; bh[nt][1] = Wh[o + 4];
                bl[nt][0] = Wl[o]; bl[nt][1] = Wl[o + 4];
            }
#pragma unroll
            for (int mt = 0; mt < 2; mt++)
#pragma unroll
                for (int nt = 0; nt < 4; nt++) {
                    mma_bf16(acc[mt][nt], ah[mt][0], ah[mt][1], ah[mt][2], ah[mt][3],
                             bh[nt][0], bh[nt][1]);
                    mma_bf16(acc[mt][nt], ah[mt][0], ah[mt][1], ah[mt][2], ah[mt][3],
                             bl[nt][0], bl[nt][1]);
                    mma_bf16(acc[mt][nt], al_[mt][0], al_[mt][1], al_[mt][2], al_[mt][3],
                             bh[nt][0], bh[nt][1]);
                }
        }

        // split + store into the OTHER buffer (no conflict with buf[cur] readers)
        if (more) {
            const int nxt = cur ^ 1;
            unsigned h0, h1, l0, l1;
            split4(av0, h0, h1, l0, l1);
            *(uint2*)&sAh[nxt][lr * 12 + lcu] = make_uint2(h0, h1);
            *(uint2*)&sAl[nxt][lr * 12 + lcu] = make_uint2(l0, l1);
            split4(av1, h0, h1, l0, l1);
            *(uint2*)&sAh[nxt][(lr + 32) * 12 + lcu] = make_uint2(h0, h1);
            *(uint2*)&sAl[nxt][(lr + 32) * 12 + lcu] = make_uint2(l0, l1);
            split4(wv0, h0, h1, l0, l1);
            *(uint2*)&sWh[nxt][lr * 12 + lcu] = make_uint2(h0, h1);
            *(uint2*)&sWl[nxt][lr * 12 + lcu] = make_uint2(l0, l1);
            split4(wv1, h0, h1, l0, l1);
            *(uint2*)&sWh[nxt][(lr + 32) * 12 + lcu] = make_uint2(h0, h1);
            *(uint2*)&sWl[nxt][(lr + 32) * 12 + lcu] = make_uint2(l0, l1);
            __syncthreads();    // one barrier per k-iteration
        }
    }

    // epilogue
#pragma unroll
    for (int mt = 0; mt < 2; mt++) {
#pragma unroll
        for (int nt = 0; nt < 4; nt++) {
            int r0 = m0 + wm + mt * 16 + (lane >> 2);
            int c0 = n0 + wn + nt * 8 + (lane & 3) * 2;
#pragma unroll
            for (int i = 0; i < 4; i++) {
                int row = r0 + (i >> 1) * 8;
                int col = c0 + (i & 1);
                if (row >= M) continue;
                float v = acc[mt][nt][i];
                if (bias) v += bias[col];
                if (add)  v += add[(size_t)row * ldc + col];
                if (act)  v = fmaxf(v, 0.f);
                C[(size_t)row * ldc + col] = v;
            }
        }
    }
}

// ---------------- pack [gru_whh ; attn_w[:,512:]] into g_Wpack [2048,512] ------
__global__ void pack_kernel(const float* __restrict__ whh,
                            const float* __restrict__ attn_w)
{
    int i = blockIdx.x * 256 + threadIdx.x;      // 0 .. 2048*512-1
    int row = i >> 9, k = i & 511;
    float v;
    if (row < 1536) v = whh[i];
    else            v = attn_w[(row - 1536) * 1024 + 512 + k];
    g_Wpack[i] = v;
}

// ---------------- features transpose: [b][cin][s] -> Xt[(b*64+s)][cin] (fp32) --
__global__ __launch_bounds__(256) void feat_transpose_kernel(
    const float* __restrict__ features)
{
    __shared__ float sm[32][65];
    const int b = blockIdx.x >> 6;          // 0..255
    const int cg = blockIdx.x & 63;         // 0..63 (32 cins each)
    const int tid = threadIdx.x;

    for (int i = tid; i < 32 * 64; i += 256) {
        int c = i >> 6, s = i & 63;
        sm[c][s] = features[((size_t)b * 2048 + cg * 32 + c) * 64 + s];
    }
    __syncthreads();
    for (int j = tid; j < 64 * 32; j += 256) {
        int s = j >> 5, c = j & 31;
        g_Xt[((size_t)b * 64 + s) * 2048 + cg * 32 + c] = sm[c][s];
    }
}

// ---------------- conv weight remap: CW[co*9+tap][cin]; rows 288..319 zero -----
__global__ void convw_pack_kernel(const float* __restrict__ conv_w)
{
    int i = blockIdx.x * 256 + threadIdx.x;      // 320*2048
    int r = i >> 11, c = i & 2047;
    float v = 0.f;
    if (r < 288) {
        int co = r / 9, tap = r % 9;
        v = conv_w[((size_t)co * 2048 + c) * 9 + tap];
    }
    g_CW[i] = v;
}

// ---------------- conv tap-reduce: Xc[b][co*64+s] = bias + sum of 9 taps -------
__global__ void conv_reduce_kernel(const float* __restrict__ conv_b)
{
    int i = blockIdx.x * 256 + threadIdx.x;      // 256*2048
    int b = i >> 11;
    int r = i & 2047;
    int co = r >> 6;
    int s = r & 63;
    int y = s >> 3, x = s & 7;
    float acc = conv_b[co];
#pragma unroll
    for (int ky = 0; ky < 3; ky++) {
        int yy = y + ky - 1;
        if (yy < 0 || yy > 7) continue;
#pragma unroll
        for (int kx = 0; kx < 3; kx++) {
            int xx = x + kx - 1;
            if (xx < 0 || xx > 7) continue;
            acc += g_ConvC[((size_t)b * 64 + yy * 8 + xx) * 320 + co * 9 + ky * 3 + kx];
        }
    }
    g_Xc[(size_t)b * 2048 + co * 64 + s] = acc;
}

// ---------------- BatchNorm1d with batch stats ---------------------------------
__global__ void bn_kernel(const float* __restrict__ bn_g,
                          const float* __restrict__ bn_b)
{
    __shared__ float red[256];
    const int h = blockIdx.x;
    const int b = threadIdx.x;
    float v = g_F0[(size_t)b * HH + h];
    red[b] = v;
    __syncthreads();
    for (int s = 128; s > 0; s >>= 1) {
        if (b < s) red[b] += red[b + s];
        __syncthreads();
    }
    float mu = red[0] / 256.f;
    __syncthreads();
    float d = v - mu;
    red[b] = d * d;
    __syncthreads();
    for (int s = 128; s > 0; s >>= 1) {
        if (b < s) red[b] += red[b + s];
        __syncthreads();
    }
    float var = red[0] / 256.f;
    float scale = rsqrtf(var + 1e-5f);
    g_F[(size_t)b * HH + h] = d * scale * bn_g[h] + bn_b[h];
}

// ---------------- gather packed embeddings into padded [T,B,E] -----------------
__global__ void gather_kernel(const int* __restrict__ pack_idx)
{
    int tb = blockIdx.x;
    int t = tb >> 8, b = tb & 255;
    int e = threadIdx.x;
    int idx = pack_idx[b * TT + t];
    float v = (idx >= 0) ? g_Emb[(size_t)idx * EE + e] : 0.f;
    g_Xpad[(size_t)tb * EE + e] = v;
}

__global__ void init_hx_kernel(const float* __restrict__ states)
{
    int i = blockIdx.x * blockDim.x + threadIdx.x;
    g_hx[i] = states[i];
}

// ---------------- softmax over h + attention gating (reads GhL L-part + xA) ----
__global__ void softmax_applied_kernel(int t)
{
    __shared__ float red[512];
    const int b = blockIdx.x;
    const int h = threadIdx.x;
    float v = g_GhL[(size_t)b * 2048 + 1536 + h]
            + g_xA[((size_t)t * BB + b) * HH + h];
    red[h] = v;
    __syncthreads();
    for (int s = 256; s > 0; s >>= 1) {
        if (h < s) red[h] = fmaxf(red[h], red[h + s]);
        __syncthreads();
    }
    float mx = red[0];
    __syncthreads();
    float e = expf(v - mx);
    red[h] = e;
    __syncthreads();
    for (int s = 256; s > 0; s >>= 1) {
        if (h < s) red[h] += red[h + s];
        __syncthreads();
    }
    float aw = e / red[0];
    g_applied[(size_t)b * HH + h] = g_F[(size_t)b * HH + h] * aw;
}

// ---------------- GRU gate combine + hidden update + capture at t==len-1 -------
__global__ void gru_gate_kernel(const int* __restrict__ lengths,
                                const float* __restrict__ gru_bhh,
                                float* __restrict__ hiddens, int t)
{
    const int b = blockIdx.x;
    const int h = threadIdx.x;
    size_t oG = (size_t)b * 2048;
    size_t oI = (size_t)b * 1536;
    float hr = g_GhL[oG + h]         + gru_bhh[h];
    float hz = g_GhL[oG + 512 + h]   + gru_bhh[512 + h];
    float hn = g_GhL[oG + 1024 + h]  + gru_bhh[1024 + h];
    float ir = g_Gi[oI + h];
    float iz = g_Gi[oI + 512 + h];
    float in_ = g_Gi[oI + 1024 + h];
    float r = 1.f / (1.f + expf(-(ir + hr)));
    float z = 1.f / (1.f + expf(-(iz + hz)));
    float n = tanhf(in_ + r * hn);
    float hprev = g_hx[(size_t)b * HH + h];
    float hnew = (1.f - z) * n + z * hprev;
    g_hx[(size_t)b * HH + h] = hnew;
    if (t == lengths[b] - 1)
        hiddens[(size_t)b * HH + h] = hnew;
}

// ---------------- build concat [hiddens, F] ------------------------------------
__global__ void cat_kernel(const float* __restrict__ hiddens)
{
    const int b = blockIdx.x;
    const int i = threadIdx.x;
    float v = (i < 512) ? hiddens[(size_t)b * HH + i]
                        : g_F[(size_t)b * HH + (i - 512)];
    g_Cat[(size_t)b * 1024 + i] = v;
}

// ---------------- final linear(1024->1) + sigmoid ------------------------------
__global__ void head_kernel(const float* __restrict__ lin3_w,
                            const float* __restrict__ lin3_b,
                            float* __restrict__ out)
{
    __shared__ float red[256];
    const int b = blockIdx.x;
    const int tid = threadIdx.x;
    float acc = 0.f;
#pragma unroll
    for (int k = 0; k < 4; k++) {
        int idx = tid + k * 256;
        acc += g_Y[(size_t)b * 1024 + idx] * lin3_w[idx];
    }
    red[tid] = acc;
    __syncthreads();
    for (int s = 128; s > 0; s >>= 1) {
        if (tid < s) red[tid] += red[tid + s];
        __syncthreads();
    }
    if (tid == 0) {
        float x = red[0] + lin3_b[0];
        out[b] = 1.f / (1.f + expf(-x));
    }
}

// ---------------- host orchestration ------------------------------------------
static void tgemm(const float* A, int lda, const float* W, int ldw,
                  const float* bias, const float* add,
                  float* C, int ldc, int M, int N, int K, int act)
{
    dim3 grid(N / 64, (M + 63) / 64);
    tgemm_kernel<<<grid, 128>>>(A, lda, W, ldw, bias, add, C, ldc, M, N, K, act);
}

extern "C" void kernel_launch(void* const* d_in, const int* in_sizes, int n_in,
                              void* d_out, int out_size)
{
    const float* features = (const float*)d_in[0];
    const float* captions = (const float*)d_in[1];
    const float* states   = (const float*)d_in[2];
    const int*   pack_idx = (const int*)d_in[3];
    const int*   lengths  = (const int*)d_in[4];
    const float* conv_w   = (const float*)d_in[5];
    const float* conv_b   = (const float*)d_in[6];
    const float* fc_w     = (const float*)d_in[7];
    const float* fc_b     = (const float*)d_in[8];
    const float* bn_g     = (const float*)d_in[9];
    const float* bn_b     = (const float*)d_in[10];
    const float* fc2_w    = (const float*)d_in[11];
    const float* fc2_b    = (const float*)d_in[12];
    const float* attn_w   = (const float*)d_in[13];
    const float* attn_b   = (const float*)d_in[14];
    const float* comb_w   = (const float*)d_in[15];
    const float* comb_b   = (const float*)d_in[16];
    const float* gru_wih  = (const float*)d_in[17];
    const float* gru_whh  = (const float*)d_in[18];
    const float* gru_bih  = (const float*)d_in[19];
    const float* gru_bhh  = (const float*)d_in[20];
    const float* lin_w    = (const float*)d_in[21];
    const float* lin_b    = (const float*)d_in[22];
    const float* lin3_w   = (const float*)d_in[23];
    const float* lin3_b   = (const float*)d_in[24];

    float* out = (float*)d_out;            // [0:256) sigmoid, [256: ) hiddens
    float* hiddens = out + 256;

    float *pXc, *pF0, *pEmb, *pXpad, *pxA, *pxC, *phx, *pGhL, *pGi;
    float *pApplied, *pInp, *pCat, *pY, *pWpack, *pXt, *pCW, *pConvC;
    cudaGetSymbolAddress((void**)&pXc, g_Xc);
    cudaGetSymbolAddress((void**)&pF0, g_F0);
    cudaGetSymbolAddress((void**)&pEmb, g_Emb);
    cudaGetSymbolAddress((void**)&pXpad, g_Xpad);
    cudaGetSymbolAddress((void**)&pxA, g_xA);
    cudaGetSymbolAddress((void**)&pxC, g_xC);
    cudaGetSymbolAddress((void**)&phx, g_hx);
    cudaGetSymbolAddress((void**)&pGhL, g_GhL);
    cudaGetSymbolAddress((void**)&pGi, g_Gi);
    cudaGetSymbolAddress((void**)&pApplied, g_applied);
    cudaGetSymbolAddress((void**)&pInp, g_inp);
    cudaGetSymbolAddress((void**)&pCat, g_Cat);
    cudaGetSymbolAddress((void**)&pY, g_Y);
    cudaGetSymbolAddress((void**)&pWpack, g_Wpack);
    cudaGetSymbolAddress((void**)&pXt, g_Xt);
    cudaGetSymbolAddress((void**)&pCW, g_CW);
    cudaGetSymbolAddress((void**)&pConvC, g_ConvC);

    // cheap independent setup
    pack_kernel<<<(2048 * 512) / 256, 256>>>(gru_whh, attn_w);
    feat_transpose_kernel<<<256 * 64, 256>>>(features);
    convw_pack_kernel<<<(320 * 2048) / 256, 256>>>(conv_w);
    init_hx_kernel<<<BB, HH>>>(states);
    // conv as GEMM: [16384 x 320 x 2048]
    tgemm(pXt, 2048, pCW, 2048, nullptr, nullptr, pConvC, 320, 16384, 320, 2048, 0);
    // captions GEMM
    tgemm(captions, VV, fc2_w, VV, fc2_b, nullptr, pEmb, EE, TTOT, EE, VV, 0);
    // conv tap reduce -> Xc
    conv_reduce_kernel<<<2048, 256>>>(conv_b);
    // fc + BN
    tgemm(pXc, 2048, fc_w, 2048, fc_b, nullptr, pF0, HH, BB, HH, 2048, 0);
    bn_kernel<<<HH, 256>>>(bn_g, bn_b);
    // gather + x-part precompute GEMMs
    gather_kernel<<<TT * BB, EE>>>(pack_idx);
    tgemm(pXpad, EE, attn_w, 1024, attn_b, nullptr, pxA, HH, TT * BB, HH, EE, 0);
    tgemm(pXpad, EE, comb_w, 1024, comb_b, nullptr, pxC, HH, TT * BB, HH, EE, 0);

    // sequential scan: 5 launches per step
    for (int t = 0; t < TT; t++) {
        tgemm(phx, HH, pWpack, HH, nullptr, nullptr, pGhL, 2048, BB, 2048, HH, 0);
        softmax_applied_kernel<<<BB, HH>>>(t);
        tgemm(pApplied, HH, comb_w + 512, 1024, nullptr,
              pxC + (size_t)t * BB * HH, pInp, HH, BB, HH, HH, 1);
        tgemm(pInp, HH, gru_wih, HH, gru_bih, nullptr, pGi, 1536, BB, 1536, HH, 0);
        gru_gate_kernel<<<BB, HH>>>(lengths, gru_bhh, hiddens, t);
    }

    // head
    cat_kernel<<<BB, 1024>>>(hiddens);
    tgemm(pCat, 1024, lin_w, 1024, lin_b, nullptr, pY, 1024, BB, 1024, 1024, 1);
    head_kernel<<<BB, 256>>>(lin3_w, lin3_b, out);
}